// round 14
// baseline (speedup 1.0000x reference)
#include <cuda_runtime.h>
#include <cuda_bf16.h>
#include <stdint.h>

#define K_DIM 4096
#define N_DIM 16384
#define M_MAX 8192

#define BM 128
#define BN 128
#define BK 64                        // bf16 elems of K per stage (128 bytes)
#define STAGES 3
#define KSTEPS (K_DIM / BK)          // 64
#define A_SMEM (BM * 128)            // 16384 bytes
#define B_SMEM (BN * 128)            // 16384 bytes
#define STAGE_BYTES (A_SMEM + B_SMEM)    // 32768
#define GEMM_SMEM (STAGES * STAGE_BYTES) // 98304 per CTA (2 CTAs/SM = 192KB)

// ---- mega-kernel block layout ----
#define QX_BLKS 8192                 // x-row quant blocks (one per row)
#define QW_PER 512                   // w-convert blocks per chunk (4096 rows)
#define GG 2048                      // gemm blocks per group (32 nt x 64 mt)
#define GROUP_SPAN (QW_PER + GG)     // 2560
#define NGROUPS 4
#define TOTAL_BLKS (QX_BLKS + NGROUPS * GROUP_SPAN)  // 18432

// ------------------------- scratch (device globals; no runtime alloc) ---
__device__ __nv_bfloat16 g_xq[(size_t)M_MAX * K_DIM];   // 64 MB bf16 x
__device__ __nv_bfloat16 g_wq[(size_t)N_DIM * K_DIM];   // 128 MB bf16 w
__device__ float g_sx[M_MAX];
__device__ unsigned g_cnt[8];        // [0]=qx done, [1..4]=qw chunk done

// ------------------------- helpers --------------------------------------
__device__ __forceinline__ uint32_t smem_u32(const void* p) {
    uint32_t a;
    asm("{ .reg .u64 t; cvta.to.shared.u64 t, %1; cvt.u32.u64 %0, t; }"
        : "=r"(a) : "l"(p));
    return a;
}
__device__ __forceinline__ uint32_t swz128(uint32_t b) { return b ^ ((b >> 3) & 0x70); }

__device__ __forceinline__ void cp_async16(uint32_t s, const void* g) {
    asm volatile("cp.async.cg.shared.global [%0], [%1], 16;" :: "r"(s), "l"(g));
}
__device__ __forceinline__ void cp_commit() {
    asm volatile("cp.async.commit_group;" ::: "memory");
}
__device__ __forceinline__ void cp_wait0() {
    asm volatile("cp.async.wait_group 0;" ::: "memory");
}
__device__ __forceinline__ void cp_wait1() {
    asm volatile("cp.async.wait_group 1;" ::: "memory");
}

__device__ __forceinline__ void ldm_x4(uint32_t* r, uint32_t addr) {
    asm volatile("ldmatrix.sync.aligned.m8n8.x4.shared.b16 {%0,%1,%2,%3}, [%4];"
        : "=r"(r[0]), "=r"(r[1]), "=r"(r[2]), "=r"(r[3]) : "r"(addr));
}

// bf16 HMMA: D(f32) += A(bf16) * B(bf16), m16n8k16
__device__ __forceinline__ void mma_bf16(float* c, const uint32_t* a, uint32_t b0, uint32_t b1) {
    asm volatile("mma.sync.aligned.m16n8k16.row.col.f32.bf16.bf16.f32 "
        "{%0,%1,%2,%3}, {%4,%5,%6,%7}, {%8,%9}, {%0,%1,%2,%3};"
        : "+f"(c[0]), "+f"(c[1]), "+f"(c[2]), "+f"(c[3])
        : "r"(a[0]), "r"(a[1]), "r"(a[2]), "r"(a[3]), "r"(b0), "r"(b1));
}

__device__ __forceinline__ uint32_t pack_bf16x2(float a, float b) {
    __nv_bfloat162 h = __floats2bfloat162_rn(a, b);
    return *reinterpret_cast<uint32_t*>(&h);
}

// =========================================================================
// mega kernel: quant producers + gemm consumers in one launch.
// Block-id layout: [qx x8192 | (qw_g x512 | gemm_g x2048) for g=0..3].
// Every gemm block waits only on strictly-lower-bid producers, and the GPU
// dispatches blocks in bid order -> no deadlock; w-chunks 1..3 convert in
// the shadow of gemm group 0.
// =========================================================================
__global__ void __launch_bounds__(128, 2) mega_kernel(const float* __restrict__ x,
                                                      const int* __restrict__ w,
                                                      const float* __restrict__ scale,
                                                      const float* __restrict__ bias,
                                                      float* __restrict__ out) {
    extern __shared__ char smem[];
    const int tid = threadIdx.x;
    const int bid = blockIdx.x;

    // =================== path 1: x-row quantization ======================
    if (bid < QX_BLKS) {
        const int row = bid;
        const float4* xv = reinterpret_cast<const float4*>(x + (size_t)row * K_DIM);

        float4 v[8];
        float m = 0.f;
#pragma unroll
        for (int i = 0; i < 8; i++) {
            v[i] = xv[tid * 8 + i];          // 32 consecutive floats / thread
            m = fmaxf(m, fmaxf(fmaxf(fabsf(v[i].x), fabsf(v[i].y)),
                               fmaxf(fabsf(v[i].z), fabsf(v[i].w))));
        }
#pragma unroll
        for (int o = 16; o; o >>= 1) m = fmaxf(m, __shfl_xor_sync(0xFFFFFFFFu, m, o));

        __shared__ float red[4];
        if ((tid & 31) == 0) red[tid >> 5] = m;
        __syncthreads();
        if (tid < 32) {
            float t = (tid < 4) ? red[tid] : 0.f;
#pragma unroll
            for (int o = 2; o; o >>= 1) t = fmaxf(t, __shfl_xor_sync(0xFFFFFFFFu, t, o));
            if (tid == 0) red[0] = t;
        }
        __syncthreads();
        float sx = red[0] / 127.0f;
        if (sx == 0.f) sx = 1.0f;
        if (tid == 0) g_sx[row] = sx;

        uint4* outp = reinterpret_cast<uint4*>(g_xq + (size_t)row * K_DIM);
#pragma unroll
        for (int j = 0; j < 4; j++) {        // 4 uint4 stores (32 bf16)
            const float4 a = v[2 * j], b = v[2 * j + 1];
            float q0 = fminf(fmaxf(rintf(a.x / sx), -127.f), 127.f);
            float q1 = fminf(fmaxf(rintf(a.y / sx), -127.f), 127.f);
            float q2 = fminf(fmaxf(rintf(a.z / sx), -127.f), 127.f);
            float q3 = fminf(fmaxf(rintf(a.w / sx), -127.f), 127.f);
            float q4 = fminf(fmaxf(rintf(b.x / sx), -127.f), 127.f);
            float q5 = fminf(fmaxf(rintf(b.y / sx), -127.f), 127.f);
            float q6 = fminf(fmaxf(rintf(b.z / sx), -127.f), 127.f);
            float q7 = fminf(fmaxf(rintf(b.w / sx), -127.f), 127.f);
            uint4 o;
            o.x = pack_bf16x2(q0, q1); o.y = pack_bf16x2(q2, q3);
            o.z = pack_bf16x2(q4, q5); o.w = pack_bf16x2(q6, q7);
            outp[tid * 4 + j] = o;
        }

        __threadfence();                     // publish row + scale
        __syncthreads();
        if (tid == 0) atomicAdd(&g_cnt[0], 1u);
        return;
    }

    const int rel = bid - QX_BLKS;
    const int g = rel / GROUP_SPAN;          // 0..3
    const int off = rel % GROUP_SPAN;

    // =================== path 2: w chunk conversion ======================
    if (off < QW_PER) {
        const long row0 = (long)g * 4096 + (long)off * 8;   // 8 rows / block
        const int4* wv = reinterpret_cast<const int4*>(w + row0 * K_DIM);
        uint4* op = reinterpret_cast<uint4*>(g_wq + row0 * K_DIM);
        // 8 rows * 4096 ints = 4096 uint4 outputs
        for (int j = tid; j < 4096; j += 128) {
            int4 a = wv[2 * j];
            int4 b = wv[2 * j + 1];
            uint4 o;
            o.x = pack_bf16x2((float)a.x, (float)a.y);
            o.y = pack_bf16x2((float)a.z, (float)a.w);
            o.z = pack_bf16x2((float)b.x, (float)b.y);
            o.w = pack_bf16x2((float)b.z, (float)b.w);
            op[j] = o;
        }
        __threadfence();
        __syncthreads();
        if (tid == 0) atomicAdd(&g_cnt[1 + g], 1u);
        return;
    }

    // =================== path 3: bf16 HMMA GEMM tile =====================
    // wait for producers: all x rows + w chunk g (strictly lower bids)
    if (tid == 0) {
        volatile unsigned* c = g_cnt;
        while (c[0] < QX_BLKS || c[1 + g] < QW_PER) __nanosleep(128);
    }
    __syncthreads();
    __threadfence();

    const int sub = off - QW_PER;            // 0..2047
    const int cg = sub >> 9;                 // raster column group (8 nt)
    const int rem = sub & 511;
    const int mt = rem >> 3;
    const int nt = g * 32 + cg * 8 + (rem & 7);
    const int n0 = nt * BN;
    const int m0 = mt * BM;

    const uint32_t sb = smem_u32(smem);
    const int wid = tid >> 5;
    const int lane = tid & 31;
    const int wm = wid >> 1;
    const int wn = wid & 1;

    // --- cp.async addressing ----------------------------------------------
    const int r0 = tid >> 3;
    const int c0 = tid & 7;
    const char* baseA = reinterpret_cast<const char*>(g_xq)
                        + (size_t)(m0 + r0) * (K_DIM * 2) + c0 * 16;
    const char* baseB = reinterpret_cast<const char*>(g_wq)
                        + (size_t)(n0 + r0) * (K_DIM * 2) + c0 * 16;
    const uint32_t sA0 = sb + swz128((uint32_t)(r0 * 128 + c0 * 16));
    const uint32_t sB0 = sA0 + A_SMEM;

    // --- ldmatrix per-lane addressing -------------------------------------
    const int q = lane >> 3;
    const int rw = lane & 7;
    const uint32_t mask = (uint32_t)rw << 4;
    const int kbA = (q >> 1) * 16;
    const int kbB = (q & 1) * 16;
    uint32_t rowA[4], rowB[4];
#pragma unroll
    for (int mi = 0; mi < 4; mi++)
        rowA[mi] = (uint32_t)((wm * 64 + mi * 16 + (q & 1) * 8 + rw) * 128);
#pragma unroll
    for (int nj = 0; nj < 4; nj++)
        rowB[nj] = (uint32_t)(A_SMEM + (wn * 64 + nj * 16 + (q >> 1) * 8 + rw) * 128);

    float acc[4][8][4];
#pragma unroll
    for (int mi = 0; mi < 4; mi++)
#pragma unroll
        for (int nj = 0; nj < 8; nj++)
#pragma unroll
            for (int t = 0; t < 4; t++) acc[mi][nj][t] = 0.f;

    auto load_stage = [&](int slot, int kblk) {
        const uint32_t soff = (uint32_t)slot * STAGE_BYTES;
        const int kb = kblk * 128;
#pragma unroll
        for (int i = 0; i < 8; i++)
            cp_async16(sA0 + soff + i * 2048u, baseA + (size_t)i * 131072 + kb);
#pragma unroll
        for (int i = 0; i < 8; i++)
            cp_async16(sB0 + soff + i * 2048u, baseB + (size_t)i * 131072 + kb);
    };

    auto load_frags = [&](uint32_t a[4][4], uint32_t b[4][4], uint32_t stg, int ks) {
        const uint32_t koffA = (uint32_t)((ks * 32 + kbA) ^ (int)mask);
        const uint32_t koffB = (uint32_t)((ks * 32 + kbB) ^ (int)mask);
#pragma unroll
        for (int mi = 0; mi < 4; mi++) ldm_x4(a[mi], stg + rowA[mi] + koffA);
#pragma unroll
        for (int nj = 0; nj < 4; nj++) ldm_x4(b[nj], stg + rowB[nj] + koffB);
    };

    uint32_t af[2][4][4], bf[2][4][4];

    auto compute_ks = [&](int pb) {
#pragma unroll
        for (int mi = 0; mi < 4; mi++) {
#pragma unroll
            for (int nj = 0; nj < 4; nj++) {
                mma_bf16(acc[mi][2 * nj + 0], af[pb][mi], bf[pb][nj][0], bf[pb][nj][1]);
                mma_bf16(acc[mi][2 * nj + 1], af[pb][mi], bf[pb][nj][2], bf[pb][nj][3]);
            }
        }
    };

    // prologue
    load_stage(0, 0); cp_commit();
    load_stage(1, 1); cp_commit();
    cp_wait1();
    __syncthreads();
    load_frags(af[0], bf[0], sb, 0);

    for (int k = 0; k < KSTEPS; k++) {
        const uint32_t stg  = sb + (uint32_t)(k % STAGES) * STAGE_BYTES;
        const uint32_t stgn = sb + (uint32_t)((k + 1) % STAGES) * STAGE_BYTES;
        const bool more = (k + 2 < KSTEPS);

        if (more) {
            load_stage((k + 2) % STAGES, k + 2);
            cp_commit();
        }

#pragma unroll
        for (int ks = 0; ks < 3; ks++) {
            const int pb = ks & 1;
            load_frags(af[pb ^ 1], bf[pb ^ 1], stg, ks + 1);
            compute_ks(pb);
        }

        if (more) cp_wait1();
        else      cp_wait0();
        __syncthreads();

        load_frags(af[0], bf[0], stgn, 0);
        compute_ks(1);
    }

    // ------------- epilogue: dequant + bias, float2 stores ---------------
    const int nbase = n0 + wn * 64;
#pragma unroll
    for (int mi = 0; mi < 4; mi++) {
        const int mlo = m0 + wm * 64 + mi * 16 + (lane >> 2);
        const int mhi = mlo + 8;
        const float slo = g_sx[mlo];
        const float shi = g_sx[mhi];
        float* orow_lo = out + (size_t)mlo * N_DIM + nbase;
        float* orow_hi = out + (size_t)mhi * N_DIM + nbase;
#pragma unroll
        for (int nj = 0; nj < 8; nj++) {
            const int n = nj * 8 + 2 * (lane & 3);
            const float2 sc = *reinterpret_cast<const float2*>(scale + nbase + n);
            const float2 bi = *reinterpret_cast<const float2*>(bias + nbase + n);
            const float* c = acc[mi][nj];
            float2 vlo, vhi;
            vlo.x = fmaf(c[0] * slo, sc.x, bi.x);
            vlo.y = fmaf(c[1] * slo, sc.y, bi.y);
            vhi.x = fmaf(c[2] * shi, sc.x, bi.x);
            vhi.y = fmaf(c[3] * shi, sc.y, bi.y);
            *reinterpret_cast<float2*>(orow_lo + n) = vlo;
            *reinterpret_cast<float2*>(orow_hi + n) = vhi;
        }
    }
}

// ------------------------- launch ---------------------------------------
extern "C" void kernel_launch(void* const* d_in, const int* in_sizes, int n_in,
                              void* d_out, int out_size) {
    const float* x = (const float*)d_in[0];
    const int* w = (const int*)d_in[1];
    const float* scale = (const float*)d_in[2];
    const float* bias = (const float*)d_in[3];
    float* out = (float*)d_out;

    static void* cnt_addr = nullptr;
    static int smem_set = 0;
    if (!smem_set) {
        cudaFuncSetAttribute(mega_kernel, cudaFuncAttributeMaxDynamicSharedMemorySize,
                             GEMM_SMEM);
        cudaGetSymbolAddress(&cnt_addr, g_cnt);
        smem_set = 1;
    }

    cudaMemsetAsync(cnt_addr, 0, 8 * sizeof(unsigned));
    mega_kernel<<<TOTAL_BLKS, 128, GEMM_SMEM>>>(x, w, scale, bias, out);
}

// round 15
// speedup vs baseline: 1.2081x; 1.2081x over previous
#include <cuda_runtime.h>
#include <cuda_bf16.h>
#include <stdint.h>

#define K_DIM 4096
#define N_DIM 16384
#define M_MAX 8192

#define BM 128
#define BN 128
#define BK 64                        // bf16 elems of K per stage (128 bytes)
#define STAGES 3
#define KSTEPS (K_DIM / BK)          // 64
#define A_SMEM (BM * 128)            // 16384 bytes
#define B_SMEM (BN * 128)            // 16384 bytes
#define STAGE_BYTES (A_SMEM + B_SMEM)    // 32768
#define GEMM_SMEM (STAGES * STAGE_BYTES) // 98304 per CTA (2 CTAs/SM = 192KB)
#define GTHREADS 128

#define TILES_M (M_MAX / BM)         // 64
#define TILES_N (N_DIM / BN)         // 128
#define RASTER_GROUP 8               // n-tiles per raster column group

#define QX_BLOCKS 8192
#define QW_BLOCKS 8192

// ------------------------- scratch (device globals; no runtime alloc) ---
__device__ __nv_bfloat16 g_xq[(size_t)M_MAX * K_DIM];   // 64 MB bf16 x
__device__ __nv_bfloat16 g_wq[(size_t)N_DIM * K_DIM];   // 128 MB bf16 w
__device__ float g_sx[M_MAX];

// ------------------------- helpers --------------------------------------
__device__ __forceinline__ uint32_t smem_u32(const void* p) {
    uint32_t a;
    asm("{ .reg .u64 t; cvta.to.shared.u64 t, %1; cvt.u32.u64 %0, t; }"
        : "=r"(a) : "l"(p));
    return a;
}
__device__ __forceinline__ uint32_t swz128(uint32_t b) { return b ^ ((b >> 3) & 0x70); }

__device__ __forceinline__ void cp_async16(uint32_t s, const void* g) {
    asm volatile("cp.async.cg.shared.global [%0], [%1], 16;" :: "r"(s), "l"(g));
}
__device__ __forceinline__ void cp_commit() {
    asm volatile("cp.async.commit_group;" ::: "memory");
}
__device__ __forceinline__ void cp_wait0() {
    asm volatile("cp.async.wait_group 0;" ::: "memory");
}
__device__ __forceinline__ void cp_wait1() {
    asm volatile("cp.async.wait_group 1;" ::: "memory");
}

__device__ __forceinline__ void ldm_x4(uint32_t* r, uint32_t addr) {
    asm volatile("ldmatrix.sync.aligned.m8n8.x4.shared.b16 {%0,%1,%2,%3}, [%4];"
        : "=r"(r[0]), "=r"(r[1]), "=r"(r[2]), "=r"(r[3]) : "r"(addr));
}

// bf16 HMMA: D(f32) += A(bf16) * B(bf16), m16n8k16
__device__ __forceinline__ void mma_bf16(float* c, const uint32_t* a, uint32_t b0, uint32_t b1) {
    asm volatile("mma.sync.aligned.m16n8k16.row.col.f32.bf16.bf16.f32 "
        "{%0,%1,%2,%3}, {%4,%5,%6,%7}, {%8,%9}, {%0,%1,%2,%3};"
        : "+f"(c[0]), "+f"(c[1]), "+f"(c[2]), "+f"(c[3])
        : "r"(a[0]), "r"(a[1]), "r"(a[2]), "r"(a[3]), "r"(b0), "r"(b1));
}

__device__ __forceinline__ uint32_t pack_bf16x2(float a, float b) {
    __nv_bfloat162 h = __floats2bfloat162_rn(a, b);
    return *reinterpret_cast<uint32_t*>(&h);
}

// streaming (evict-first) float2 store: keeps L2 for the GEMM's A/B tiles
__device__ __forceinline__ void stg_cs_f2(float* p, float a, float b) {
    asm volatile("st.global.cs.v2.f32 [%0], {%1, %2};" :: "l"(p), "f"(a), "f"(b)
                 : "memory");
}

// ------------------- kernel 1: fused quantize (x rows + w convert) -------
__global__ void __launch_bounds__(256) quant_fused_kernel(const float* __restrict__ x,
                                                          const int* __restrict__ w) {
    if (blockIdx.x < QX_BLOCKS) {
        // ---- x row quantization: one block per row -----------------------
        const int row = blockIdx.x;
        const float4* xv = reinterpret_cast<const float4*>(x + (size_t)row * K_DIM);

        float4 v[4];
        float m = 0.f;
#pragma unroll
        for (int i = 0; i < 4; i++) {
            v[i] = xv[threadIdx.x * 4 + i];
            m = fmaxf(m, fmaxf(fmaxf(fabsf(v[i].x), fabsf(v[i].y)),
                               fmaxf(fabsf(v[i].z), fabsf(v[i].w))));
        }
#pragma unroll
        for (int o = 16; o; o >>= 1) m = fmaxf(m, __shfl_xor_sync(0xFFFFFFFFu, m, o));

        __shared__ float sm[8];
        if ((threadIdx.x & 31) == 0) sm[threadIdx.x >> 5] = m;
        __syncthreads();
        if (threadIdx.x < 32) {
            float t = (threadIdx.x < 8) ? sm[threadIdx.x] : 0.f;
#pragma unroll
            for (int o = 4; o; o >>= 1) t = fmaxf(t, __shfl_xor_sync(0xFFFFFFFFu, t, o));
            if (threadIdx.x == 0) sm[0] = t;
        }
        __syncthreads();
        float sx = sm[0] / 127.0f;
        if (sx == 0.f) sx = 1.0f;
        if (threadIdx.x == 0) g_sx[row] = sx;

        uint4 o1, o2;
        float qv[16];
#pragma unroll
        for (int i = 0; i < 4; i++) {
            qv[4 * i + 0] = fminf(fmaxf(rintf(v[i].x / sx), -127.f), 127.f);
            qv[4 * i + 1] = fminf(fmaxf(rintf(v[i].y / sx), -127.f), 127.f);
            qv[4 * i + 2] = fminf(fmaxf(rintf(v[i].z / sx), -127.f), 127.f);
            qv[4 * i + 3] = fminf(fmaxf(rintf(v[i].w / sx), -127.f), 127.f);
        }
        o1.x = pack_bf16x2(qv[0], qv[1]);   o1.y = pack_bf16x2(qv[2], qv[3]);
        o1.z = pack_bf16x2(qv[4], qv[5]);   o1.w = pack_bf16x2(qv[6], qv[7]);
        o2.x = pack_bf16x2(qv[8], qv[9]);   o2.y = pack_bf16x2(qv[10], qv[11]);
        o2.z = pack_bf16x2(qv[12], qv[13]); o2.w = pack_bf16x2(qv[14], qv[15]);
        uint4* outp = reinterpret_cast<uint4*>(g_xq + (size_t)row * K_DIM);
        outp[threadIdx.x * 2 + 0] = o1;
        outp[threadIdx.x * 2 + 1] = o2;
    } else {
        // ---- weight int32 -> bf16 convert, 8 independent int4 loads ------
        // total outputs: N*K/8 uint4 = 8M; 4 outputs per thread per iter
        const long total4 = (long)N_DIM * K_DIM / 32;  // groups of 4 uint4
        long gid = (blockIdx.x - QX_BLOCKS) * 256L + threadIdx.x;
        const long stride = QW_BLOCKS * 256L;
        const int4* wv = reinterpret_cast<const int4*>(w);
        uint4* out = reinterpret_cast<uint4*>(g_wq);
        for (; gid < total4; gid += stride) {
            int4 in[8];
#pragma unroll
            for (int i = 0; i < 8; i++) in[i] = wv[gid * 8 + i];   // MLP = 8
#pragma unroll
            for (int j = 0; j < 4; j++) {
                const int4 a = in[2 * j], b = in[2 * j + 1];
                uint4 o;
                o.x = pack_bf16x2((float)a.x, (float)a.y);
                o.y = pack_bf16x2((float)a.z, (float)a.w);
                o.z = pack_bf16x2((float)b.x, (float)b.y);
                o.w = pack_bf16x2((float)b.z, (float)b.w);
                out[gid * 4 + j] = o;
            }
        }
    }
}

// ------------------------- kernel 2: bf16 HMMA GEMM ----------------------
// 128x128 CTA tile, 4 warps (2 M x 2 N), 64x64 warp tiles, 2 CTAs/SM.
// 3-stage cp.async pipeline, hoisted loads (R13 ordering, proven correct):
//   top:   load_stage(k+2) -> slot (k-1)%3 ; commit   (overlaps ks0-2)
//   ks0-2: prefetch(stage k, ks+1) + MMA
//          wait_group 1 (stage k+1 complete) ; __syncthreads (publish)
//   ks3:   prefetch(stage k+1, ks0) + MMA
__global__ void __launch_bounds__(GTHREADS, 2) gemm_kernel(float* __restrict__ out,
                                                           const float* __restrict__ scale,
                                                           const float* __restrict__ bias) {
    extern __shared__ char smem[];
    const uint32_t sb = smem_u32(smem);
    const int tid = threadIdx.x;
    const int wid = tid >> 5;           // 0..3
    const int lane = tid & 31;

    // ---- L2-friendly rasterization ---------------------------------------
    const int bid = blockIdx.x;
    const int group = bid / (RASTER_GROUP * TILES_M);
    const int rem = bid % (RASTER_GROUP * TILES_M);
    const int mt = rem / RASTER_GROUP;
    const int nt = group * RASTER_GROUP + (rem % RASTER_GROUP);
    const int n0 = nt * BN;
    const int m0 = mt * BM;

    const int wm = wid >> 1;            // 0..1
    const int wn = wid & 1;             // 0..1

    // --- cp.async addressing ----------------------------------------------
    const int r0 = tid >> 3;            // 0..15
    const int c0 = tid & 7;             // 0..7 (16B chunk in row)
    const char* baseA = reinterpret_cast<const char*>(g_xq)
                        + (size_t)(m0 + r0) * (K_DIM * 2) + c0 * 16;
    const char* baseB = reinterpret_cast<const char*>(g_wq)
                        + (size_t)(n0 + r0) * (K_DIM * 2) + c0 * 16;
    const uint32_t sA0 = sb + swz128((uint32_t)(r0 * 128 + c0 * 16));
    const uint32_t sB0 = sA0 + A_SMEM;  // +16384: swizzle-safe offset

    // --- ldmatrix per-lane addressing -------------------------------------
    const int q = lane >> 3;
    const int rw = lane & 7;
    const uint32_t mask = (uint32_t)rw << 4;
    const int kbA = (q >> 1) * 16;
    const int kbB = (q & 1) * 16;
    uint32_t rowA[4], rowB[4];
#pragma unroll
    for (int mi = 0; mi < 4; mi++)
        rowA[mi] = (uint32_t)((wm * 64 + mi * 16 + (q & 1) * 8 + rw) * 128);
#pragma unroll
    for (int nj = 0; nj < 4; nj++)
        rowB[nj] = (uint32_t)(A_SMEM + (wn * 64 + nj * 16 + (q >> 1) * 8 + rw) * 128);

    float acc[4][8][4];
#pragma unroll
    for (int mi = 0; mi < 4; mi++)
#pragma unroll
        for (int nj = 0; nj < 8; nj++)
#pragma unroll
            for (int t = 0; t < 4; t++) acc[mi][nj][t] = 0.f;

    // --- stage loader: 8 A-chunks + 8 B-chunks of 16B per thread ----------
    auto load_stage = [&](int slot, int kblk) {
        const uint32_t soff = (uint32_t)slot * STAGE_BYTES;
        const int kb = kblk * 128;
#pragma unroll
        for (int i = 0; i < 8; i++)     // A: 128 rows, 16 rows per step
            cp_async16(sA0 + soff + i * 2048u, baseA + (size_t)i * 131072 + kb);
#pragma unroll
        for (int i = 0; i < 8; i++)     // B: 128 rows
            cp_async16(sB0 + soff + i * 2048u, baseB + (size_t)i * 131072 + kb);
    };

    // --- fragment loader ----------------------------------------------------
    auto load_frags = [&](uint32_t a[4][4], uint32_t b[4][4], uint32_t stg, int ks) {
        const uint32_t koffA = (uint32_t)((ks * 32 + kbA) ^ (int)mask);
        const uint32_t koffB = (uint32_t)((ks * 32 + kbB) ^ (int)mask);
#pragma unroll
        for (int mi = 0; mi < 4; mi++) ldm_x4(a[mi], stg + rowA[mi] + koffA);
#pragma unroll
        for (int nj = 0; nj < 4; nj++) ldm_x4(b[nj], stg + rowB[nj] + koffB);
    };

    uint32_t af[2][4][4], bf[2][4][4];

    auto compute_ks = [&](int pb) {
#pragma unroll
        for (int mi = 0; mi < 4; mi++) {
#pragma unroll
            for (int nj = 0; nj < 4; nj++) {
                mma_bf16(acc[mi][2 * nj + 0], af[pb][mi], bf[pb][nj][0], bf[pb][nj][1]);
                mma_bf16(acc[mi][2 * nj + 1], af[pb][mi], bf[pb][nj][2], bf[pb][nj][3]);
            }
        }
    };

    // prologue: stages 0,1 in flight; publish stage 0; preload ks=0 frags
    load_stage(0, 0); cp_commit();
    load_stage(1, 1); cp_commit();
    cp_wait1();                          // stage 0 own-complete
    __syncthreads();                     // publish stage 0 to all threads
    load_frags(af[0], bf[0], sb, 0);     // stage 0, ks=0

    for (int k = 0; k < KSTEPS; k++) {
        const uint32_t stg  = sb + (uint32_t)(k % STAGES) * STAGE_BYTES;
        const uint32_t stgn = sb + (uint32_t)((k + 1) % STAGES) * STAGE_BYTES;
        const bool more = (k + 2 < KSTEPS);

        // hoisted load: slot (k-1)%3 is free (readers finished pre-barrier)
        if (more) {
            load_stage((k + 2) % STAGES, k + 2);
            cp_commit();
        }

        // ks = 0..2: stage k was published at iteration k-1's sync
#pragma unroll
        for (int ks = 0; ks < 3; ks++) {
            const int pb = ks & 1;
            load_frags(af[pb ^ 1], bf[pb ^ 1], stg, ks + 1);
            compute_ks(pb);
        }

        // stage k+1 complete (k+2 may stay pending when issued), then publish
        if (more) cp_wait1();
        else      cp_wait0();
        __syncthreads();

        // ks = 3: prefetch (k+1, ks=0) from just-published stage k+1
        load_frags(af[0], bf[0], stgn, 0);
        compute_ks(1);
    }

    // ---- epilogue: dequant + bias, streaming (evict-first) stores --------
    const int nbase = n0 + wn * 64;
#pragma unroll
    for (int mi = 0; mi < 4; mi++) {
        const int mlo = m0 + wm * 64 + mi * 16 + (lane >> 2);
        const int mhi = mlo + 8;
        const float slo = g_sx[mlo];
        const float shi = g_sx[mhi];
        float* orow_lo = out + (size_t)mlo * N_DIM + nbase;
        float* orow_hi = out + (size_t)mhi * N_DIM + nbase;
#pragma unroll
        for (int nj = 0; nj < 8; nj++) {
            const int n = nj * 8 + 2 * (lane & 3);
            const float2 sc = *reinterpret_cast<const float2*>(scale + nbase + n);
            const float2 bi = *reinterpret_cast<const float2*>(bias + nbase + n);
            const float* c = acc[mi][nj];
            stg_cs_f2(orow_lo + n, fmaf(c[0] * slo, sc.x, bi.x),
                                   fmaf(c[1] * slo, sc.y, bi.y));
            stg_cs_f2(orow_hi + n, fmaf(c[2] * shi, sc.x, bi.x),
                                   fmaf(c[3] * shi, sc.y, bi.y));
        }
    }
}

// ------------------------- launch ---------------------------------------
extern "C" void kernel_launch(void* const* d_in, const int* in_sizes, int n_in,
                              void* d_out, int out_size) {
    const float* x = (const float*)d_in[0];
    const int* w = (const int*)d_in[1];
    const float* scale = (const float*)d_in[2];
    const float* bias = (const float*)d_in[3];
    float* out = (float*)d_out;

    static int smem_set = 0;
    if (!smem_set) {
        cudaFuncSetAttribute(gemm_kernel, cudaFuncAttributeMaxDynamicSharedMemorySize,
                             GEMM_SMEM);
        smem_set = 1;
    }

    quant_fused_kernel<<<QX_BLOCKS + QW_BLOCKS, 256>>>(x, w);
    gemm_kernel<<<TILES_M * TILES_N, GTHREADS, GEMM_SMEM>>>(out, scale, bias);
}

// round 16
// speedup vs baseline: 1.2239x; 1.0131x over previous
#include <cuda_runtime.h>
#include <cuda_bf16.h>
#include <stdint.h>

#define K_DIM 4096
#define N_DIM 16384
#define M_MAX 8192

#define BM 128
#define BN 128
#define BK 64                        // bf16 elems of K per stage (128 bytes)
#define STAGES 3
#define KSTEPS (K_DIM / BK)          // 64
#define A_SMEM (BM * 128)            // 16384 bytes
#define B_SMEM (BN * 128)            // 16384 bytes
#define STAGE_BYTES (A_SMEM + B_SMEM)    // 32768
#define GEMM_SMEM (STAGES * STAGE_BYTES) // 98304 per CTA (2 CTAs/SM = 192KB)
#define GTHREADS 128

#define TILES_M (M_MAX / BM)         // 64
#define TILES_N (N_DIM / BN)         // 128
#define RASTER_GROUP 8               // n-tiles per raster column group

#define QX_BLOCKS 8192
#define QW_BLOCKS 16384

// ------------------------- scratch (device globals; no runtime alloc) ---
__device__ __nv_bfloat16 g_xq[(size_t)M_MAX * K_DIM];   // 64 MB bf16 x
__device__ __nv_bfloat16 g_wq[(size_t)N_DIM * K_DIM];   // 128 MB bf16 w
__device__ float g_sx[M_MAX];

// ------------------------- helpers --------------------------------------
__device__ __forceinline__ uint32_t smem_u32(const void* p) {
    uint32_t a;
    asm("{ .reg .u64 t; cvta.to.shared.u64 t, %1; cvt.u32.u64 %0, t; }"
        : "=r"(a) : "l"(p));
    return a;
}
__device__ __forceinline__ uint32_t swz128(uint32_t b) { return b ^ ((b >> 3) & 0x70); }

__device__ __forceinline__ void cp_async16(uint32_t s, const void* g) {
    asm volatile("cp.async.cg.shared.global [%0], [%1], 16;" :: "r"(s), "l"(g));
}
__device__ __forceinline__ void cp_commit() {
    asm volatile("cp.async.commit_group;" ::: "memory");
}
__device__ __forceinline__ void cp_wait0() {
    asm volatile("cp.async.wait_group 0;" ::: "memory");
}
__device__ __forceinline__ void cp_wait1() {
    asm volatile("cp.async.wait_group 1;" ::: "memory");
}

__device__ __forceinline__ void ldm_x4(uint32_t* r, uint32_t addr) {
    asm volatile("ldmatrix.sync.aligned.m8n8.x4.shared.b16 {%0,%1,%2,%3}, [%4];"
        : "=r"(r[0]), "=r"(r[1]), "=r"(r[2]), "=r"(r[3]) : "r"(addr));
}

// bf16 HMMA: D(f32) += A(bf16) * B(bf16), m16n8k16
__device__ __forceinline__ void mma_bf16(float* c, const uint32_t* a, uint32_t b0, uint32_t b1) {
    asm volatile("mma.sync.aligned.m16n8k16.row.col.f32.bf16.bf16.f32 "
        "{%0,%1,%2,%3}, {%4,%5,%6,%7}, {%8,%9}, {%0,%1,%2,%3};"
        : "+f"(c[0]), "+f"(c[1]), "+f"(c[2]), "+f"(c[3])
        : "r"(a[0]), "r"(a[1]), "r"(a[2]), "r"(a[3]), "r"(b0), "r"(b1));
}

__device__ __forceinline__ uint32_t pack_bf16x2(float a, float b) {
    __nv_bfloat162 h = __floats2bfloat162_rn(a, b);
    return *reinterpret_cast<uint32_t*>(&h);
}

// ------------------- kernel 1: fused quantize (x rows + w convert) -------
__global__ void __launch_bounds__(256) quant_fused_kernel(const float* __restrict__ x,
                                                          const int* __restrict__ w) {
    if (blockIdx.x < QX_BLOCKS) {
        // ---- x row quantization: one block per row -----------------------
        const int row = blockIdx.x;
        const float4* xv = reinterpret_cast<const float4*>(x + (size_t)row * K_DIM);

        float4 v[4];
        float m = 0.f;
#pragma unroll
        for (int i = 0; i < 4; i++) {
            v[i] = xv[threadIdx.x * 4 + i];
            m = fmaxf(m, fmaxf(fmaxf(fabsf(v[i].x), fabsf(v[i].y)),
                               fmaxf(fabsf(v[i].z), fabsf(v[i].w))));
        }
#pragma unroll
        for (int o = 16; o; o >>= 1) m = fmaxf(m, __shfl_xor_sync(0xFFFFFFFFu, m, o));

        __shared__ float sm[8];
        if ((threadIdx.x & 31) == 0) sm[threadIdx.x >> 5] = m;
        __syncthreads();
        if (threadIdx.x < 32) {
            float t = (threadIdx.x < 8) ? sm[threadIdx.x] : 0.f;
#pragma unroll
            for (int o = 4; o; o >>= 1) t = fmaxf(t, __shfl_xor_sync(0xFFFFFFFFu, t, o));
            if (threadIdx.x == 0) sm[0] = t;
        }
        __syncthreads();
        float sx = sm[0] / 127.0f;
        if (sx == 0.f) sx = 1.0f;
        if (threadIdx.x == 0) g_sx[row] = sx;

        uint4 o1, o2;
        float qv[16];
#pragma unroll
        for (int i = 0; i < 4; i++) {
            qv[4 * i + 0] = fminf(fmaxf(rintf(v[i].x / sx), -127.f), 127.f);
            qv[4 * i + 1] = fminf(fmaxf(rintf(v[i].y / sx), -127.f), 127.f);
            qv[4 * i + 2] = fminf(fmaxf(rintf(v[i].z / sx), -127.f), 127.f);
            qv[4 * i + 3] = fminf(fmaxf(rintf(v[i].w / sx), -127.f), 127.f);
        }
        o1.x = pack_bf16x2(qv[0], qv[1]);   o1.y = pack_bf16x2(qv[2], qv[3]);
        o1.z = pack_bf16x2(qv[4], qv[5]);   o1.w = pack_bf16x2(qv[6], qv[7]);
        o2.x = pack_bf16x2(qv[8], qv[9]);   o2.y = pack_bf16x2(qv[10], qv[11]);
        o2.z = pack_bf16x2(qv[12], qv[13]); o2.w = pack_bf16x2(qv[14], qv[15]);
        uint4* outp = reinterpret_cast<uint4*>(g_xq + (size_t)row * K_DIM);
        outp[threadIdx.x * 2 + 0] = o1;
        outp[threadIdx.x * 2 + 1] = o2;
    } else {
        // ---- weight int32 -> bf16 convert ---------------------------------
        const long total8 = (long)N_DIM * K_DIM / 8;
        long gid = (blockIdx.x - QX_BLOCKS) * 256L + threadIdx.x;
        const long stride = QW_BLOCKS * 256L;
        const int4* wv = reinterpret_cast<const int4*>(w);
        uint4* out = reinterpret_cast<uint4*>(g_wq);
        for (; gid < total8; gid += stride) {
            int4 a = wv[gid * 2 + 0];
            int4 b = wv[gid * 2 + 1];
            uint4 o;
            o.x = pack_bf16x2((float)a.x, (float)a.y);
            o.y = pack_bf16x2((float)a.z, (float)a.w);
            o.z = pack_bf16x2((float)b.x, (float)b.y);
            o.w = pack_bf16x2((float)b.z, (float)b.w);
            out[gid] = o;
        }
    }
}

// ------------------------- kernel 2: bf16 HMMA GEMM ----------------------
// 128x128 CTA tile, 4 warps (2 M x 2 N), 64x64 warp tiles, 2 CTAs/SM.
// 3-stage cp.async pipeline, hoisted loads (R13 ordering, proven correct),
// with the next-ks ldmatrix prefetch INTERLEAVED between MMA groups so the
// tensor pipe never drains during an LDSM burst.
__global__ void __launch_bounds__(GTHREADS, 2) gemm_kernel(float* __restrict__ out,
                                                           const float* __restrict__ scale,
                                                           const float* __restrict__ bias) {
    extern __shared__ char smem[];
    const uint32_t sb = smem_u32(smem);
    const int tid = threadIdx.x;
    const int wid = tid >> 5;           // 0..3
    const int lane = tid & 31;

    // ---- L2-friendly rasterization ---------------------------------------
    const int bid = blockIdx.x;
    const int group = bid / (RASTER_GROUP * TILES_M);
    const int rem = bid % (RASTER_GROUP * TILES_M);
    const int mt = rem / RASTER_GROUP;
    const int nt = group * RASTER_GROUP + (rem % RASTER_GROUP);
    const int n0 = nt * BN;
    const int m0 = mt * BM;

    const int wm = wid >> 1;            // 0..1
    const int wn = wid & 1;             // 0..1

    // --- cp.async addressing ----------------------------------------------
    const int r0 = tid >> 3;            // 0..15
    const int c0 = tid & 7;             // 0..7 (16B chunk in row)
    const char* baseA = reinterpret_cast<const char*>(g_xq)
                        + (size_t)(m0 + r0) * (K_DIM * 2) + c0 * 16;
    const char* baseB = reinterpret_cast<const char*>(g_wq)
                        + (size_t)(n0 + r0) * (K_DIM * 2) + c0 * 16;
    const uint32_t sA0 = sb + swz128((uint32_t)(r0 * 128 + c0 * 16));
    const uint32_t sB0 = sA0 + A_SMEM;  // +16384: swizzle-safe offset

    // --- ldmatrix per-lane addressing -------------------------------------
    const int q = lane >> 3;
    const int rw = lane & 7;
    const uint32_t mask = (uint32_t)rw << 4;
    const int kbA = (q >> 1) * 16;
    const int kbB = (q & 1) * 16;
    uint32_t rowA[4], rowB[4];
#pragma unroll
    for (int mi = 0; mi < 4; mi++)
        rowA[mi] = (uint32_t)((wm * 64 + mi * 16 + (q & 1) * 8 + rw) * 128);
#pragma unroll
    for (int nj = 0; nj < 4; nj++)
        rowB[nj] = (uint32_t)(A_SMEM + (wn * 64 + nj * 16 + (q >> 1) * 8 + rw) * 128);

    float acc[4][8][4];
#pragma unroll
    for (int mi = 0; mi < 4; mi++)
#pragma unroll
        for (int nj = 0; nj < 8; nj++)
#pragma unroll
            for (int t = 0; t < 4; t++) acc[mi][nj][t] = 0.f;

    // --- stage loader: 8 A-chunks + 8 B-chunks of 16B per thread ----------
    auto load_stage = [&](int slot, int kblk) {
        const uint32_t soff = (uint32_t)slot * STAGE_BYTES;
        const int kb = kblk * 128;
#pragma unroll
        for (int i = 0; i < 8; i++)     // A: 128 rows, 16 rows per step
            cp_async16(sA0 + soff + i * 2048u, baseA + (size_t)i * 131072 + kb);
#pragma unroll
        for (int i = 0; i < 8; i++)     // B: 128 rows
            cp_async16(sB0 + soff + i * 2048u, baseB + (size_t)i * 131072 + kb);
    };

    // --- fragment loader (burst form, for prologue) ------------------------
    auto load_frags = [&](uint32_t a[4][4], uint32_t b[4][4], uint32_t stg, int ks) {
        const uint32_t koffA = (uint32_t)((ks * 32 + kbA) ^ (int)mask);
        const uint32_t koffB = (uint32_t)((ks * 32 + kbB) ^ (int)mask);
#pragma unroll
        for (int mi = 0; mi < 4; mi++) ldm_x4(a[mi], stg + rowA[mi] + koffA);
#pragma unroll
        for (int nj = 0; nj < 4; nj++) ldm_x4(b[nj], stg + rowB[nj] + koffB);
    };

    uint32_t af[2][4][4], bf[2][4][4];

    // 4 MMAs on accumulator block (mi, nj0..nj0+1) using buffer pb
#define MMA_GRP(pb, mi, nj0)                                                     \
        mma_bf16(acc[mi][2*(nj0)+0], af[pb][mi], bf[pb][nj0][0], bf[pb][nj0][1]); \
        mma_bf16(acc[mi][2*(nj0)+1], af[pb][mi], bf[pb][nj0][2], bf[pb][nj0][3]); \
        mma_bf16(acc[mi][2*(nj0)+2], af[pb][mi], bf[pb][(nj0)+1][0], bf[pb][(nj0)+1][1]); \
        mma_bf16(acc[mi][2*(nj0)+3], af[pb][mi], bf[pb][(nj0)+1][2], bf[pb][(nj0)+1][3]);

    // interleaved step: compute 32 MMAs on buffer pb while loading the next
    // fragments (stage stg_src, step ks_src) into buffer pb^1, one ldmatrix
    // between each 4-MMA group (asm volatile order is preserved).
    auto step = [&](int pb, uint32_t stg_src, int ks_src) {
        const int nb = pb ^ 1;
        const uint32_t koffA = (uint32_t)((ks_src * 32 + kbA) ^ (int)mask);
        const uint32_t koffB = (uint32_t)((ks_src * 32 + kbB) ^ (int)mask);
        ldm_x4(af[nb][0], stg_src + rowA[0] + koffA);  MMA_GRP(pb, 0, 0)
        ldm_x4(af[nb][1], stg_src + rowA[1] + koffA);  MMA_GRP(pb, 0, 2)
        ldm_x4(af[nb][2], stg_src + rowA[2] + koffA);  MMA_GRP(pb, 1, 0)
        ldm_x4(af[nb][3], stg_src + rowA[3] + koffA);  MMA_GRP(pb, 1, 2)
        ldm_x4(bf[nb][0], stg_src + rowB[0] + koffB);  MMA_GRP(pb, 2, 0)
        ldm_x4(bf[nb][1], stg_src + rowB[1] + koffB);  MMA_GRP(pb, 2, 2)
        ldm_x4(bf[nb][2], stg_src + rowB[2] + koffB);  MMA_GRP(pb, 3, 0)
        ldm_x4(bf[nb][3], stg_src + rowB[3] + koffB);  MMA_GRP(pb, 3, 2)
    };

    // prologue: stages 0,1 in flight; publish stage 0; preload ks=0 frags
    load_stage(0, 0); cp_commit();
    load_stage(1, 1); cp_commit();
    cp_wait1();                          // stage 0 own-complete
    __syncthreads();                     // publish stage 0 to all threads
    load_frags(af[0], bf[0], sb, 0);     // stage 0, ks=0

    for (int k = 0; k < KSTEPS; k++) {
        const uint32_t stg  = sb + (uint32_t)(k % STAGES) * STAGE_BYTES;
        const uint32_t stgn = sb + (uint32_t)((k + 1) % STAGES) * STAGE_BYTES;
        const bool more = (k + 2 < KSTEPS);

        // hoisted load: slot (k-1)%3 is free (readers finished pre-barrier)
        if (more) {
            load_stage((k + 2) % STAGES, k + 2);
            cp_commit();
        }

        // ks = 0..2: stage k was published at iteration k-1's sync
        step(0, stg, 1);
        step(1, stg, 2);
        step(0, stg, 3);

        // stage k+1 complete (k+2 may stay pending when issued), then publish
        if (more) cp_wait1();
        else      cp_wait0();
        __syncthreads();

        // ks = 3: prefetch (k+1, ks=0) from just-published stage k+1
        step(1, stgn, 0);
    }

    // ------------- epilogue: dequant + bias, float2 stores ---------------
    const int nbase = n0 + wn * 64;
#pragma unroll
    for (int mi = 0; mi < 4; mi++) {
        const int mlo = m0 + wm * 64 + mi * 16 + (lane >> 2);
        const int mhi = mlo + 8;
        const float slo = g_sx[mlo];
        const float shi = g_sx[mhi];
        float* orow_lo = out + (size_t)mlo * N_DIM + nbase;
        float* orow_hi = out + (size_t)mhi * N_DIM + nbase;
#pragma unroll
        for (int nj = 0; nj < 8; nj++) {
            const int n = nj * 8 + 2 * (lane & 3);
            const float2 sc = *reinterpret_cast<const float2*>(scale + nbase + n);
            const float2 bi = *reinterpret_cast<const float2*>(bias + nbase + n);
            const float* c = acc[mi][nj];
            float2 vlo, vhi;
            vlo.x = fmaf(c[0] * slo, sc.x, bi.x);
            vlo.y = fmaf(c[1] * slo, sc.y, bi.y);
            vhi.x = fmaf(c[2] * shi, sc.x, bi.x);
            vhi.y = fmaf(c[3] * shi, sc.y, bi.y);
            *reinterpret_cast<float2*>(orow_lo + n) = vlo;
            *reinterpret_cast<float2*>(orow_hi + n) = vhi;
        }
    }
#undef MMA_GRP
}

// ------------------------- launch ---------------------------------------
extern "C" void kernel_launch(void* const* d_in, const int* in_sizes, int n_in,
                              void* d_out, int out_size) {
    const float* x = (const float*)d_in[0];
    const int* w = (const int*)d_in[1];
    const float* scale = (const float*)d_in[2];
    const float* bias = (const float*)d_in[3];
    float* out = (float*)d_out;

    static int smem_set = 0;
    if (!smem_set) {
        cudaFuncSetAttribute(gemm_kernel, cudaFuncAttributeMaxDynamicSharedMemorySize,
                             GEMM_SMEM);
        smem_set = 1;
    }

    quant_fused_kernel<<<QX_BLOCKS + QW_BLOCKS, 256>>>(x, w);
    gemm_kernel<<<TILES_M * TILES_N, GTHREADS, GEMM_SMEM>>>(out, scale, bias);
}